// round 2
// baseline (speedup 1.0000x reference)
#include <cuda_runtime.h>

#define LSEQ 384
#define DSEQ 256
#define H    32
#define P    128

// scratch (allocation-free rule: __device__ globals)
__device__ float g_s1[LSEQ * H];
__device__ float g_s2[LSEQ * H];
__device__ float g_T[(size_t)LSEQ * P * H];   // [i][p][f], 6.3 MB

typedef unsigned long long u64;

__device__ __forceinline__ u64 pk(float lo, float hi) {
    u64 r; asm("mov.b64 %0,{%1,%2};" : "=l"(r) : "f"(lo), "f"(hi)); return r;
}
__device__ __forceinline__ void upk(u64 v, float& lo, float& hi) {
    asm("mov.b64 {%0,%1},%2;" : "=f"(lo), "=f"(hi) : "l"(v));
}
__device__ __forceinline__ void fma2(u64& d, u64 a, u64 b) {
    asm("fma.rn.f32x2 %0,%1,%2,%3;" : "=l"(d) : "l"(a), "l"(b), "l"(d));
}

// ---------------------------------------------------------------------------
// Kernel A: LayerNorm + the two 256->32 projections. One block per sequence row.
// ---------------------------------------------------------------------------
__global__ __launch_bounds__(256) void ln_proj_kernel(
    const float* __restrict__ seq,
    const float* __restrict__ gamma, const float* __restrict__ beta,
    const float* __restrict__ w1, const float* __restrict__ b1,
    const float* __restrict__ w2, const float* __restrict__ b2)
{
    int i = blockIdx.x;
    int t = threadIdx.x;
    __shared__ float xs[DSEQ];
    __shared__ float2 wred[8];

    float v = seq[i * DSEQ + t];
    float s = v, q = v * v;
    #pragma unroll
    for (int o = 16; o; o >>= 1) {
        s += __shfl_down_sync(0xffffffffu, s, o);
        q += __shfl_down_sync(0xffffffffu, q, o);
    }
    if ((t & 31) == 0) wred[t >> 5] = make_float2(s, q);
    __syncthreads();

    float ts = 0.f, tq = 0.f;
    #pragma unroll
    for (int k = 0; k < 8; k++) { ts += wred[k].x; tq += wred[k].y; }
    float mu   = ts * (1.f / DSEQ);
    float var  = tq * (1.f / DSEQ) - mu * mu;
    float rstd = rsqrtf(var + 1e-5f);

    xs[t] = (v - mu) * rstd * gamma[t] + beta[t];
    __syncthreads();

    int w = t >> 5, l = t & 31;
    const float* W    = (w < 4) ? w1 : w2;
    const float* bias = (w < 4) ? b1 : b2;
    float* outp       = (w < 4) ? g_s1 : g_s2;
    int hbase = (w & 3) * 8;
    #pragma unroll
    for (int o = 0; o < 8; o++) {
        int h = hbase + o;
        float acc = 0.f;
        #pragma unroll
        for (int k = 0; k < 8; k++)
            acc += xs[l + 32 * k] * W[h * DSEQ + l + 32 * k];
        #pragma unroll
        for (int off = 16; off; off >>= 1)
            acc += __shfl_down_sync(0xffffffffu, acc, off);
        if (l == 0) outp[i * H + h] = acc + bias[h];
    }
}

// ---------------------------------------------------------------------------
// Kernel B: T[i,p,f] = sum_d s1[i,d] * w3[p, d*32+f].  One block per p.
// ---------------------------------------------------------------------------
__global__ __launch_bounds__(256) void t_kernel(const float* __restrict__ w3)
{
    int p = blockIdx.x;
    __shared__ float w3s[H * H];   // [d][f]
    __shared__ float rows[8][H];   // per-warp s1 row staging

    for (int idx = threadIdx.x; idx < H * H; idx += 256)
        w3s[idx] = w3[p * (H * H) + idx];
    __syncthreads();

    int f = threadIdx.x & 31, iw = threadIdx.x >> 5;
    for (int r = 0; r < LSEQ / 8; r++) {
        int i = r * 8 + iw;
        rows[iw][f] = g_s1[i * H + f];     // coalesced, warp-private
        __syncwarp();
        float acc = 0.f;
        #pragma unroll
        for (int d = 0; d < H; d++)
            acc += rows[iw][d] * w3s[d * H + f];
        g_T[(size_t)i * (P * H) + p * H + f] = acc;
        __syncwarp();
    }
}

// ---------------------------------------------------------------------------
// Kernel C: pair[i,j,p] = b3[p] + sum_f T[i,p,f] * s2[j,f]
// Block = (i, 128-wide j tile). 256 threads, 8j x 8p register tile per thread,
// packed f32x2 FMAs (2 FMAs/issue on the fma pipe).
// Shared layouts are [f][...] with stride 132 floats (=528B, 16B-aligned rows)
// so per-f LDS.128 of pair data is conflict-free (f is loop-uniform).
// ---------------------------------------------------------------------------
__global__ __launch_bounds__(256) void pair_kernel(
    const float* __restrict__ b3, float* __restrict__ out)
{
    int i     = blockIdx.x;
    int jbase = blockIdx.y * 128;
    __shared__ __align__(16) float Ts[H * 132];    // [f][p]
    __shared__ __align__(16) float s2s[H * 132];   // [f][j]
    int tid = threadIdx.x;

    for (int idx = tid; idx < P * H; idx += 256) {
        int p = idx >> 5, f = idx & 31;
        Ts[f * 132 + p] = g_T[(size_t)i * (P * H) + idx];   // coalesced read
    }
    for (int idx = tid; idx < 128 * H; idx += 256) {
        int j = idx >> 5, f = idx & 31;
        s2s[f * 132 + j] = g_s2[(jbase + j) * H + f];       // coalesced read
    }
    __syncthreads();

    int tx = tid & 15, ty = tid >> 4;   // tx -> p (4+4 cols), ty -> j (8 rows)
    u64 acc[8][4];
    {
        float4 c0 = *(const float4*)(b3 + tx * 4);
        float4 c1 = *(const float4*)(b3 + 64 + tx * 4);
        u64 i0 = pk(c0.x, c0.y), i1 = pk(c0.z, c0.w);
        u64 i2 = pk(c1.x, c1.y), i3 = pk(c1.z, c1.w);
        #pragma unroll
        for (int jj = 0; jj < 8; jj++) {
            acc[jj][0] = i0; acc[jj][1] = i1; acc[jj][2] = i2; acc[jj][3] = i3;
        }
    }

    const float* srow = s2s + ty * 8;
    #pragma unroll 4
    for (int f = 0; f < H; ++f) {
        const float* tr = Ts + f * 132;
        ulonglong2 B0 = *(const ulonglong2*)(const void*)(tr + tx * 4);
        ulonglong2 B1 = *(const ulonglong2*)(const void*)(tr + 64 + tx * 4);
        const float* ar = srow + f * 132;
        #pragma unroll
        for (int jj = 0; jj < 8; jj++) {
            float a = ar[jj];
            u64 a2 = pk(a, a);
            fma2(acc[jj][0], a2, B0.x);
            fma2(acc[jj][1], a2, B0.y);
            fma2(acc[jj][2], a2, B1.x);
            fma2(acc[jj][3], a2, B1.y);
        }
    }

    float* obase = out + ((size_t)i * LSEQ + jbase + ty * 8) * P;
    #pragma unroll
    for (int jj = 0; jj < 8; jj++) {
        float4 v;
        upk(acc[jj][0], v.x, v.y); upk(acc[jj][1], v.z, v.w);
        *(float4*)(obase + (size_t)jj * P + tx * 4) = v;
        upk(acc[jj][2], v.x, v.y); upk(acc[jj][3], v.z, v.w);
        *(float4*)(obase + (size_t)jj * P + 64 + tx * 4) = v;
    }
}

extern "C" void kernel_launch(void* const* d_in, const int* in_sizes, int n_in,
                              void* d_out, int out_size)
{
    const float* seq   = (const float*)d_in[0];
    const float* gamma = (const float*)d_in[1];
    const float* beta  = (const float*)d_in[2];
    const float* w1    = (const float*)d_in[3];
    const float* b1    = (const float*)d_in[4];
    const float* w2    = (const float*)d_in[5];
    const float* b2    = (const float*)d_in[6];
    const float* w3    = (const float*)d_in[7];
    const float* b3    = (const float*)d_in[8];

    ln_proj_kernel<<<LSEQ, 256>>>(seq, gamma, beta, w1, b1, w2, b2);
    t_kernel<<<P, 256>>>(w3);
    pair_kernel<<<dim3(LSEQ, 3), 256>>>(b3, (float*)d_out);
}

// round 3
// speedup vs baseline: 1.3510x; 1.3510x over previous
#include <cuda_runtime.h>

#define LSEQ 384
#define DSEQ 256
#define H    32
#define P    128

// scratch (allocation-free rule: __device__ globals)
__device__ float g_s1[LSEQ * H];
__device__ float g_s2[LSEQ * H];
__device__ float g_T[(size_t)LSEQ * P * H];   // [i][p][f], 6.3 MB

typedef unsigned long long u64;

__device__ __forceinline__ u64 pk(float lo, float hi) {
    u64 r; asm("mov.b64 %0,{%1,%2};" : "=l"(r) : "f"(lo), "f"(hi)); return r;
}
__device__ __forceinline__ void upk(u64 v, float& lo, float& hi) {
    asm("mov.b64 {%0,%1},%2;" : "=f"(lo), "=f"(hi) : "l"(v));
}
__device__ __forceinline__ void fma2(u64& d, u64 a, u64 b) {
    asm("fma.rn.f32x2 %0,%1,%2,%3;" : "=l"(d) : "l"(a), "l"(b), "l"(d));
}

// ---------------------------------------------------------------------------
// Kernel A: LayerNorm + the two 256->32 projections. One block per sequence row.
// ---------------------------------------------------------------------------
__global__ __launch_bounds__(256) void ln_proj_kernel(
    const float* __restrict__ seq,
    const float* __restrict__ gamma, const float* __restrict__ beta,
    const float* __restrict__ w1, const float* __restrict__ b1,
    const float* __restrict__ w2, const float* __restrict__ b2)
{
    int i = blockIdx.x;
    int t = threadIdx.x;
    __shared__ float xs[DSEQ];
    __shared__ float2 wred[8];

    float v = seq[i * DSEQ + t];
    float s = v, q = v * v;
    #pragma unroll
    for (int o = 16; o; o >>= 1) {
        s += __shfl_down_sync(0xffffffffu, s, o);
        q += __shfl_down_sync(0xffffffffu, q, o);
    }
    if ((t & 31) == 0) wred[t >> 5] = make_float2(s, q);
    __syncthreads();

    float ts = 0.f, tq = 0.f;
    #pragma unroll
    for (int k = 0; k < 8; k++) { ts += wred[k].x; tq += wred[k].y; }
    float mu   = ts * (1.f / DSEQ);
    float var  = tq * (1.f / DSEQ) - mu * mu;
    float rstd = rsqrtf(var + 1e-5f);

    xs[t] = (v - mu) * rstd * gamma[t] + beta[t];
    __syncthreads();

    int w = t >> 5, l = t & 31;
    const float* W    = (w < 4) ? w1 : w2;
    const float* bias = (w < 4) ? b1 : b2;
    float* outp       = (w < 4) ? g_s1 : g_s2;
    int hbase = (w & 3) * 8;
    #pragma unroll
    for (int o = 0; o < 8; o++) {
        int h = hbase + o;
        float acc = 0.f;
        #pragma unroll
        for (int k = 0; k < 8; k++)
            acc += xs[l + 32 * k] * W[h * DSEQ + l + 32 * k];
        #pragma unroll
        for (int off = 16; off; off >>= 1)
            acc += __shfl_down_sync(0xffffffffu, acc, off);
        if (l == 0) outp[i * H + h] = acc + bias[h];
    }
}

// ---------------------------------------------------------------------------
// Kernel B: T[i,p,f] = sum_d s1[i,d] * w3[p, d*32+f].
// Grid (128 p, 4 i-slices) -> 512 blocks for better SM coverage.
// ---------------------------------------------------------------------------
__global__ __launch_bounds__(256) void t_kernel(const float* __restrict__ w3)
{
    int p  = blockIdx.x;
    int i0 = blockIdx.y * (LSEQ / 4);
    __shared__ float w3s[H * H];   // [d][f]
    __shared__ float rows[8][H];   // per-warp s1 row staging

    for (int idx = threadIdx.x; idx < H * H; idx += 256)
        w3s[idx] = w3[p * (H * H) + idx];
    __syncthreads();

    int f = threadIdx.x & 31, iw = threadIdx.x >> 5;
    for (int r = 0; r < LSEQ / 4 / 8; r++) {
        int i = i0 + r * 8 + iw;
        rows[iw][f] = g_s1[i * H + f];     // coalesced, warp-private
        __syncwarp();
        float acc = 0.f;
        #pragma unroll
        for (int d = 0; d < H; d++)
            acc += rows[iw][d] * w3s[d * H + f];
        g_T[(size_t)i * (P * H) + p * H + f] = acc;
        __syncwarp();
    }
}

// ---------------------------------------------------------------------------
// Kernel C: pair[i,j,p] = b3[p] + sum_f T[i,p,f] * s2[j,f]
// Block = (i, 128-wide j tile). 256 threads, 8j x 8p register tile per thread,
// packed f32x2 FMAs. s2 values are PRE-DUPLICATED into shared as (a,a) u64
// pairs so the hot loop has zero register-pair packing: per f it is exactly
// 6x LDS.128 + 32x FFMA2. Strides of 132 keep rows 16B-aligned; in-loop f is
// warp-uniform so all vector LDS are conflict-free.
// ---------------------------------------------------------------------------
__global__ __launch_bounds__(256, 2) void pair_kernel(
    const float* __restrict__ b3, float* __restrict__ out)
{
    int i     = blockIdx.x;
    int jbase = blockIdx.y * 128;
    __shared__ __align__(16) float Ts [H * 132];   // [f][p]   floats
    __shared__ __align__(16) u64   s2d[H * 132];   // [f][j]   (a,a) pairs
    int tid = threadIdx.x;

    #pragma unroll
    for (int k = 0; k < 16; k++) {
        int idx = tid + k * 256;                 // 4096 total
        int p = idx >> 5, f = idx & 31;
        Ts[f * 132 + p] = g_T[(size_t)i * (P * H) + idx];   // coalesced read
    }
    #pragma unroll
    for (int k = 0; k < 16; k++) {
        int idx = tid + k * 256;                 // 4096 total
        int j = idx >> 5, f = idx & 31;
        float a = g_s2[(jbase + j) * H + f];                 // coalesced read
        s2d[f * 132 + j] = pk(a, a);
    }
    __syncthreads();

    int tx = tid & 15, ty = tid >> 4;   // tx -> p (4+4 cols), ty -> j (8 rows)
    u64 acc[8][4];
    {
        float4 c0 = *(const float4*)(b3 + tx * 4);
        float4 c1 = *(const float4*)(b3 + 64 + tx * 4);
        u64 i0 = pk(c0.x, c0.y), i1 = pk(c0.z, c0.w);
        u64 i2 = pk(c1.x, c1.y), i3 = pk(c1.z, c1.w);
        #pragma unroll
        for (int jj = 0; jj < 8; jj++) {
            acc[jj][0] = i0; acc[jj][1] = i1; acc[jj][2] = i2; acc[jj][3] = i3;
        }
    }

    const u64* arow = s2d + ty * 8;
    #pragma unroll 4
    for (int f = 0; f < H; ++f) {
        const float* tr = Ts + f * 132;
        ulonglong2 B0 = *(const ulonglong2*)(const void*)(tr + tx * 4);
        ulonglong2 B1 = *(const ulonglong2*)(const void*)(tr + 64 + tx * 4);
        const u64* ar = arow + f * 132;
        ulonglong2 A0 = *(const ulonglong2*)(const void*)(ar + 0);
        ulonglong2 A1 = *(const ulonglong2*)(const void*)(ar + 2);
        ulonglong2 A2 = *(const ulonglong2*)(const void*)(ar + 4);
        ulonglong2 A3 = *(const ulonglong2*)(const void*)(ar + 6);
        u64 a2[8] = {A0.x, A0.y, A1.x, A1.y, A2.x, A2.y, A3.x, A3.y};
        #pragma unroll
        for (int jj = 0; jj < 8; jj++) {
            fma2(acc[jj][0], a2[jj], B0.x);
            fma2(acc[jj][1], a2[jj], B0.y);
            fma2(acc[jj][2], a2[jj], B1.x);
            fma2(acc[jj][3], a2[jj], B1.y);
        }
    }

    float* obase = out + ((size_t)i * LSEQ + jbase + ty * 8) * P;
    #pragma unroll
    for (int jj = 0; jj < 8; jj++) {
        float4 v;
        upk(acc[jj][0], v.x, v.y); upk(acc[jj][1], v.z, v.w);
        *(float4*)(obase + (size_t)jj * P + tx * 4) = v;
        upk(acc[jj][2], v.x, v.y); upk(acc[jj][3], v.z, v.w);
        *(float4*)(obase + (size_t)jj * P + 64 + tx * 4) = v;
    }
}

extern "C" void kernel_launch(void* const* d_in, const int* in_sizes, int n_in,
                              void* d_out, int out_size)
{
    const float* seq   = (const float*)d_in[0];
    const float* gamma = (const float*)d_in[1];
    const float* beta  = (const float*)d_in[2];
    const float* w1    = (const float*)d_in[3];
    const float* b1    = (const float*)d_in[4];
    const float* w2    = (const float*)d_in[5];
    const float* b2    = (const float*)d_in[6];
    const float* w3    = (const float*)d_in[7];
    const float* b3    = (const float*)d_in[8];

    ln_proj_kernel<<<LSEQ, 256>>>(seq, gamma, beta, w1, b1, w2, b2);
    t_kernel<<<dim3(P, 4), 256>>>(w3);
    pair_kernel<<<dim3(LSEQ, 3), 256>>>(b3, (float*)d_out);
}

// round 5
// speedup vs baseline: 1.3564x; 1.0040x over previous
#include <cuda_runtime.h>
#include <cstdint>

#define LSEQ 384
#define DSEQ 256
#define H    32
#define P    128

// scratch (allocation-free rule: __device__ globals)
__device__ float g_s1[LSEQ * H];
__device__ float g_s2[LSEQ * H];
__device__ float g_T[(size_t)LSEQ * P * H];   // [i][p][f], 6.3 MB

__device__ __forceinline__ void split_tf32(float x, uint32_t& hi, uint32_t& lo) {
    asm("cvt.rna.tf32.f32 %0, %1;" : "=r"(hi) : "f"(x));
    float l = x - __uint_as_float(hi);
    asm("cvt.rna.tf32.f32 %0, %1;" : "=r"(lo) : "f"(l));
}

__device__ __forceinline__ void mma_tf32(float* d, const uint4& a, const uint2& b) {
    asm("mma.sync.aligned.m16n8k8.row.col.f32.tf32.tf32.f32 "
        "{%0,%1,%2,%3},{%4,%5,%6,%7},{%8,%9},{%0,%1,%2,%3};"
        : "+f"(d[0]), "+f"(d[1]), "+f"(d[2]), "+f"(d[3])
        : "r"(a.x), "r"(a.y), "r"(a.z), "r"(a.w), "r"(b.x), "r"(b.y));
}

// ---------------------------------------------------------------------------
// Kernel A: LayerNorm + the two 256->32 projections. One block per sequence row.
// Proj uses per-lane contiguous float4 weight loads (16 LDG.128 in flight).
// ---------------------------------------------------------------------------
__global__ __launch_bounds__(256) void ln_proj_kernel(
    const float* __restrict__ seq,
    const float* __restrict__ gamma, const float* __restrict__ beta,
    const float* __restrict__ w1, const float* __restrict__ b1,
    const float* __restrict__ w2, const float* __restrict__ b2)
{
    int i = blockIdx.x;
    int t = threadIdx.x;
    __shared__ float xs[DSEQ];
    __shared__ float2 wred[8];

    float v = seq[i * DSEQ + t];
    float s = v, q = v * v;
    #pragma unroll
    for (int o = 16; o; o >>= 1) {
        s += __shfl_down_sync(0xffffffffu, s, o);
        q += __shfl_down_sync(0xffffffffu, q, o);
    }
    if ((t & 31) == 0) wred[t >> 5] = make_float2(s, q);
    __syncthreads();

    float ts = 0.f, tq = 0.f;
    #pragma unroll
    for (int k = 0; k < 8; k++) { ts += wred[k].x; tq += wred[k].y; }
    float mu   = ts * (1.f / DSEQ);
    float var  = tq * (1.f / DSEQ) - mu * mu;
    float rstd = rsqrtf(var + 1e-5f);

    xs[t] = (v - mu) * rstd * gamma[t] + beta[t];
    __syncthreads();

    int w = t >> 5, l = t & 31;
    const float* W    = (w < 4) ? w1 : w2;
    const float* bias = (w < 4) ? b1 : b2;
    float* outp       = (w < 4) ? g_s1 : g_s2;
    int hbase = (w & 3) * 8;

    float4 x0 = *(const float4*)(xs + l * 8);
    float4 x1 = *(const float4*)(xs + l * 8 + 4);

    #pragma unroll
    for (int o = 0; o < 8; o++) {
        int h = hbase + o;
        const float4* Wr = (const float4*)(W + h * DSEQ + l * 8);
        float4 a0 = __ldg(Wr), a1 = __ldg(Wr + 1);
        float acc = x0.x*a0.x + x0.y*a0.y + x0.z*a0.z + x0.w*a0.w
                  + x1.x*a1.x + x1.y*a1.y + x1.z*a1.z + x1.w*a1.w;
        #pragma unroll
        for (int off = 16; off; off >>= 1)
            acc += __shfl_down_sync(0xffffffffu, acc, off);
        if (l == 0) outp[i * H + h] = acc + bias[h];
    }
}

// ---------------------------------------------------------------------------
// Kernel B: T[i,p,f] = sum_d s1[i,d] * w3[p, d*32+f].
// ---------------------------------------------------------------------------
__global__ __launch_bounds__(256) void t_kernel(const float* __restrict__ w3)
{
    int p  = blockIdx.x;
    int i0 = blockIdx.y * (LSEQ / 4);
    __shared__ float w3s[H * H];   // [d][f]
    __shared__ float rows[8][H];

    for (int idx = threadIdx.x; idx < H * H; idx += 256)
        w3s[idx] = w3[p * (H * H) + idx];
    __syncthreads();

    int f = threadIdx.x & 31, iw = threadIdx.x >> 5;
    for (int r = 0; r < LSEQ / 4 / 8; r++) {
        int i = i0 + r * 8 + iw;
        rows[iw][f] = g_s1[i * H + f];
        __syncwarp();
        float acc = 0.f;
        #pragma unroll
        for (int d = 0; d < H; d++)
            acc += rows[iw][d] * w3s[d * H + f];
        g_T[(size_t)i * (P * H) + p * H + f] = acc;
        __syncwarp();
    }
}

// ---------------------------------------------------------------------------
// Kernel C: pair[i,j,p] = b3[p] + sum_f S2[j,f] * T_i[p,f]   via mma.sync tf32
// CTA = (i, 128-j tile), 256 threads = 8 warps in 2(m) x 4(n) grid;
// warp tile m64 x n32, k=32 in 4 steps of k8; 3xTF32 compensated passes.
// SMEM holds operands PRE-SPLIT (hi/lo tf32) in exact m16n8k8 fragment order:
//   AH/AL: [kt][m16-tile][lane][4 regs]   (LDS.128, conflict-free)
//   BH/BL: [kt][n8-tile][lane][2 regs]    (LDS.64,  conflict-free)
// ---------------------------------------------------------------------------
#define SM_AH 0
#define SM_AL 16384
#define SM_BH 32768
#define SM_BL 49152
#define SM_TOTAL 65536

__global__ __launch_bounds__(256) void pair_mma_kernel(
    const float* __restrict__ b3, float* __restrict__ out)
{
    extern __shared__ __align__(16) char smem[];
    int tid = threadIdx.x;
    int i = blockIdx.x, jbase = blockIdx.y * 128;

    // ---- fill A fragments (S2 tile: rows j, k = f) ----
    const float* As = g_s2 + (size_t)jbase * H;
    #pragma unroll
    for (int it = 0; it < 4; it++) {
        int base = (tid + it * 256) * 4;        // 4 consecutive frag floats
        int lane = (base >> 2) & 31;
        int rest = base >> 7;
        int mf = rest & 7, kt = rest >> 3;
        int r = mf * 16 + (lane >> 2);
        int c = kt * 8 + (lane & 3);
        float v0 = __ldg(As + r * H + c);             // a0: (r,   c)
        float v1 = __ldg(As + (r + 8) * H + c);       // a1: (r+8, c)
        float v2 = __ldg(As + r * H + c + 4);         // a2: (r,   c+4)
        float v3 = __ldg(As + (r + 8) * H + c + 4);   // a3: (r+8, c+4)
        uint4 hi, lo;
        split_tf32(v0, hi.x, lo.x); split_tf32(v1, hi.y, lo.y);
        split_tf32(v2, hi.z, lo.z); split_tf32(v3, hi.w, lo.w);
        *(uint4*)(smem + SM_AH + base * 4) = hi;
        *(uint4*)(smem + SM_AL + base * 4) = lo;
    }
    // ---- fill B fragments (T_i tile: cols p, k = f) ----
    const float* Bs = g_T + (size_t)i * (P * H);
    #pragma unroll
    for (int it = 0; it < 4; it++) {
        int base = (tid + it * 256) * 4;        // covers lanes {la, la+1}, q={0,1}
        int la   = (base >> 1) & 31;            // even
        int rest = base >> 6;
        int nf = rest & 15, kt = rest >> 4;
        int p = nf * 8 + (la >> 2);
        int f = kt * 8 + (la & 3);
        float v0 = __ldg(Bs + p * H + f);          // lane la,   b0: k=f
        float v1 = __ldg(Bs + p * H + f + 4);      // lane la,   b1: k=f+4
        float v2 = __ldg(Bs + p * H + f + 1);      // lane la+1, b0
        float v3 = __ldg(Bs + p * H + f + 5);      // lane la+1, b1
        uint4 hi, lo;
        split_tf32(v0, hi.x, lo.x); split_tf32(v1, hi.y, lo.y);
        split_tf32(v2, hi.z, lo.z); split_tf32(v3, hi.w, lo.w);
        *(uint4*)(smem + SM_BH + base * 4) = hi;
        *(uint4*)(smem + SM_BL + base * 4) = lo;
    }

    int wid = tid >> 5, lane = tid & 31;
    int wm = wid >> 2, wn = wid & 3;

    // init accumulators with bias (c0,c1 @ row r; c2,c3 @ row r+8; cols 2t,2t+1)
    float acc[4][4][4];
    #pragma unroll
    for (int nt = 0; nt < 4; nt++) {
        float2 bv = __ldg((const float2*)(b3 + wn * 32 + nt * 8 + (lane & 3) * 2));
        #pragma unroll
        for (int mt = 0; mt < 4; mt++) {
            acc[mt][nt][0] = bv.x; acc[mt][nt][1] = bv.y;
            acc[mt][nt][2] = bv.x; acc[mt][nt][3] = bv.y;
        }
    }
    __syncthreads();

    // ---- main loop: 4 k-steps, 3 compensated passes each ----
    #pragma unroll
    for (int kt = 0; kt < 4; kt++) {
        uint2 bh[4], bl[4];
        #pragma unroll
        for (int nt = 0; nt < 4; nt++) {
            int off = ((kt * 16 + wn * 4 + nt) * 32 + lane) * 8;
            bh[nt] = *(const uint2*)(smem + SM_BH + off);
            bl[nt] = *(const uint2*)(smem + SM_BL + off);
        }
        #pragma unroll
        for (int mt = 0; mt < 4; mt++) {
            int aoff = ((kt * 8 + wm * 4 + mt) * 32 + lane) * 16;
            uint4 ah = *(const uint4*)(smem + SM_AH + aoff);
            uint4 al = *(const uint4*)(smem + SM_AL + aoff);
            #pragma unroll
            for (int nt = 0; nt < 4; nt++) {
                mma_tf32(acc[mt][nt], ah, bh[nt]);
                mma_tf32(acc[mt][nt], ah, bl[nt]);
                mma_tf32(acc[mt][nt], al, bh[nt]);
            }
        }
    }

    // ---- epilogue: direct float2 stores ----
    #pragma unroll
    for (int mt = 0; mt < 4; mt++) {
        int row = jbase + wm * 64 + mt * 16 + (lane >> 2);
        float* o0 = out + ((size_t)i * LSEQ + row) * P + wn * 32 + (lane & 3) * 2;
        #pragma unroll
        for (int nt = 0; nt < 4; nt++) {
            *(float2*)(o0 + nt * 8)         = make_float2(acc[mt][nt][0], acc[mt][nt][1]);
            *(float2*)(o0 + 8 * P + nt * 8) = make_float2(acc[mt][nt][2], acc[mt][nt][3]);
        }
    }
}

extern "C" void kernel_launch(void* const* d_in, const int* in_sizes, int n_in,
                              void* d_out, int out_size)
{
    const float* seq   = (const float*)d_in[0];
    const float* gamma = (const float*)d_in[1];
    const float* beta  = (const float*)d_in[2];
    const float* w1    = (const float*)d_in[3];
    const float* b1    = (const float*)d_in[4];
    const float* w2    = (const float*)d_in[5];
    const float* b2    = (const float*)d_in[6];
    const float* w3    = (const float*)d_in[7];
    const float* b3    = (const float*)d_in[8];

    cudaFuncSetAttribute(pair_mma_kernel,
                         cudaFuncAttributeMaxDynamicSharedMemorySize, SM_TOTAL);

    ln_proj_kernel<<<LSEQ, 256>>>(seq, gamma, beta, w1, b1, w2, b2);
    t_kernel<<<dim3(P, 4), 256>>>(w3);
    pair_mma_kernel<<<dim3(LSEQ, 3), 256, SM_TOTAL>>>(b3, (float*)d_out);
}

// round 6
// speedup vs baseline: 1.6641x; 1.2268x over previous
#include <cuda_runtime.h>
#include <cuda_bf16.h>
#include <cstdint>

#define LSEQ 384
#define DSEQ 256
#define H    32
#define P    128

// ---------------------------------------------------------------------------
// scratch (__device__ globals; allocation-free rule)
// ---------------------------------------------------------------------------
__device__ float g_s1[LSEQ * H];
__device__ float g_s2[LSEQ * H];
__device__ float g_T[(size_t)LSEQ * P * H];        // [i][n=p*32+f] fp32

// Pre-built m16n8k16 bf16 fragments (hi/lo planes for 3xBF16)
__device__ uint4 g_Abh[3 * 512],  g_Abl[3 * 512];   // S2  A-frags, per j-tile
__device__ uint4 g_As1h[3 * 512], g_As1l[3 * 512];  // s1  A-frags, per i-tile
__device__ uint4 g_Tbh[LSEQ * 512], g_Tbl[LSEQ * 512]; // T B-frags per i (uint2 pairs)

// ---------------------------------------------------------------------------
// helpers
// ---------------------------------------------------------------------------
// pack bf16(x0) -> low half, bf16(x1) -> high half; also return residuals pack
__device__ __forceinline__ void split_pair(float x0, float x1,
                                           uint32_t& h, uint32_t& l) {
    asm("cvt.rn.bf16x2.f32 %0, %1, %2;" : "=r"(h) : "f"(x1), "f"(x0));
    float r0 = x0 - __uint_as_float(h << 16);
    float r1 = x1 - __uint_as_float(h & 0xffff0000u);
    asm("cvt.rn.bf16x2.f32 %0, %1, %2;" : "=r"(l) : "f"(r1), "f"(r0));
}

__device__ __forceinline__ void mma_bf16(float* d, const uint4& a, const uint2& b) {
    asm("mma.sync.aligned.m16n8k16.row.col.f32.bf16.bf16.f32 "
        "{%0,%1,%2,%3},{%4,%5,%6,%7},{%8,%9},{%0,%1,%2,%3};"
        : "+f"(d[0]), "+f"(d[1]), "+f"(d[2]), "+f"(d[3])
        : "r"(a.x), "r"(a.y), "r"(a.z), "r"(a.w), "r"(b.x), "r"(b.y));
}

// shared 128x128 (K=32) bf16x3 mainloop: warp grid 2(m) x 4(n), warp tile 64x32
__device__ __forceinline__ void gemm_compute(
    const uint4* sAH, const uint4* sAL, const uint2* sBH, const uint2* sBL,
    int wm, int wn, int lane, float acc[4][4][4])
{
    #pragma unroll
    for (int kt = 0; kt < 2; kt++) {
        uint2 bh[4], bl[4];
        #pragma unroll
        for (int nt = 0; nt < 4; nt++) {
            int bi = (kt * 16 + wn * 4 + nt) * 32 + lane;
            bh[nt] = sBH[bi]; bl[nt] = sBL[bi];
        }
        #pragma unroll
        for (int mt = 0; mt < 4; mt++) {
            int ai = (kt * 8 + wm * 4 + mt) * 32 + lane;
            uint4 ah = sAH[ai], al = sAL[ai];
            #pragma unroll
            for (int nt = 0; nt < 4; nt++) {
                mma_bf16(acc[mt][nt], ah, bh[nt]);
                mma_bf16(acc[mt][nt], ah, bl[nt]);
                mma_bf16(acc[mt][nt], al, bh[nt]);
            }
        }
    }
}

// ---------------------------------------------------------------------------
// Kernel A: LayerNorm + two 256->32 projections. Block per row.
// Projection: 64 dots x 4 threads, 16 indep LDG.128 each, quad-shfl reduce.
// ---------------------------------------------------------------------------
__global__ __launch_bounds__(256) void ln_proj_kernel(
    const float* __restrict__ seq,
    const float* __restrict__ gamma, const float* __restrict__ beta,
    const float* __restrict__ w1, const float* __restrict__ b1,
    const float* __restrict__ w2, const float* __restrict__ b2)
{
    int i = blockIdx.x;
    int t = threadIdx.x;
    __shared__ float xs[DSEQ];
    __shared__ float2 wred[8];

    float v = seq[i * DSEQ + t];
    float s = v, q = v * v;
    #pragma unroll
    for (int o = 16; o; o >>= 1) {
        s += __shfl_down_sync(0xffffffffu, s, o);
        q += __shfl_down_sync(0xffffffffu, q, o);
    }
    if ((t & 31) == 0) wred[t >> 5] = make_float2(s, q);
    __syncthreads();

    float ts = 0.f, tq = 0.f;
    #pragma unroll
    for (int k = 0; k < 8; k++) { ts += wred[k].x; tq += wred[k].y; }
    float mu   = ts * (1.f / DSEQ);
    float var  = tq * (1.f / DSEQ) - mu * mu;
    float rstd = rsqrtf(var + 1e-5f);

    xs[t] = (v - mu) * rstd * gamma[t] + beta[t];
    __syncthreads();

    int dot = t >> 2, quarter = t & 3;
    int which = dot >> 5, h = dot & 31;
    const float* W    = which ? w2 : w1;
    const float* bias = which ? b2 : b1;
    float* outp       = which ? g_s2 : g_s1;

    const float4* Wr = (const float4*)(W + h * DSEQ + quarter * 64);
    const float4* Xr = (const float4*)(xs + quarter * 64);
    float acc = 0.f;
    #pragma unroll
    for (int k = 0; k < 16; k++) {
        float4 a = __ldg(Wr + k);
        float4 x = Xr[k];
        acc += a.x * x.x + a.y * x.y + a.z * x.z + a.w * x.w;
    }
    acc += __shfl_down_sync(0xffffffffu, acc, 1);
    acc += __shfl_down_sync(0xffffffffu, acc, 2);
    if (quarter == 0) outp[i * H + h] = acc + bias[h];
}

// ---------------------------------------------------------------------------
// asplit: pre-build A fragments (hi/lo bf16) for S2 (blocks 0-5) and s1 (6-11)
// item = ((tile*2+kt)*8+mt)*32+lane;  r = tile*128+mt*16+(lane>>2), c = kt*16+2t
// ---------------------------------------------------------------------------
__global__ __launch_bounds__(256) void asplit_kernel()
{
    int gid = blockIdx.x * 256 + threadIdx.x;      // 0..3071
    int sel = gid >= 1536;
    int idx = sel ? gid - 1536 : gid;
    const float* src = sel ? g_s1 : g_s2;
    uint4* dh = sel ? g_As1h : g_Abh;
    uint4* dl = sel ? g_As1l : g_Abl;

    int lane = idx & 31, rest = idx >> 5;
    int mt = rest & 7, kt = (rest >> 3) & 1, tile = rest >> 4;
    int r = tile * 128 + mt * 16 + (lane >> 2);
    int c = kt * 16 + (lane & 3) * 2;

    float2 v00 = *(const float2*)(src + r * H + c);         // a0
    float2 v10 = *(const float2*)(src + (r + 8) * H + c);   // a1
    float2 v01 = *(const float2*)(src + r * H + c + 8);     // a2
    float2 v11 = *(const float2*)(src + (r + 8) * H + c + 8); // a3
    uint4 hi, lo;
    split_pair(v00.x, v00.y, hi.x, lo.x);
    split_pair(v10.x, v10.y, hi.y, lo.y);
    split_pair(v01.x, v01.y, hi.z, lo.z);
    split_pair(v11.x, v11.y, hi.w, lo.w);
    dh[idx] = hi; dl[idx] = lo;
}

// ---------------------------------------------------------------------------
// tgemm: T[i, n] = sum_d s1[i,d] * w3[n>>5, d*32 + (n&31)]   (M=384,N=4096,K=32)
// CTA = (itile, ntile): 128x128 tile, bf16x3 HMMA.
// ---------------------------------------------------------------------------
__global__ __launch_bounds__(256) void tgemm_kernel(const float* __restrict__ w3)
{
    __shared__ uint4 sAH[512], sAL[512];
    __shared__ uint2 sBH[1024], sBL[1024];
    int tid = threadIdx.x, lane = tid & 31;
    int itile = blockIdx.x, ntile = blockIdx.y;

    // A frags: copy pre-split s1 fragments
    sAH[tid]       = g_As1h[itile * 512 + tid];
    sAH[tid + 256] = g_As1h[itile * 512 + tid + 256];
    sAL[tid]       = g_As1l[itile * 512 + tid];
    sAL[tid + 256] = g_As1l[itile * 512 + tid + 256];

    // B frags: gather w3 and split
    #pragma unroll
    for (int k = 0; k < 4; k++) {
        int t = tid + k * 256;                      // 0..1023
        int la = t & 31, nt = (t >> 5) & 15, kt = t >> 9;
        int n = ntile * 128 + nt * 8 + (la >> 2);
        int p = n >> 5, f = n & 31;
        int d0 = kt * 16 + (la & 3) * 2;
        const float* wp = w3 + p * (H * H);
        float v00 = __ldg(wp + d0 * H + f);
        float v01 = __ldg(wp + (d0 + 1) * H + f);
        float v10 = __ldg(wp + (d0 + 8) * H + f);
        float v11 = __ldg(wp + (d0 + 9) * H + f);
        uint32_t b0h, b0l, b1h, b1l;
        split_pair(v00, v01, b0h, b0l);
        split_pair(v10, v11, b1h, b1l);
        sBH[t] = make_uint2(b0h, b1h);
        sBL[t] = make_uint2(b0l, b1l);
    }

    float acc[4][4][4];
    #pragma unroll
    for (int a = 0; a < 4; a++)
        #pragma unroll
        for (int b = 0; b < 4; b++)
            #pragma unroll
            for (int c = 0; c < 4; c++) acc[a][b][c] = 0.f;
    __syncthreads();

    int wid = tid >> 5, wm = wid >> 2, wn = wid & 3;
    gemm_compute(sAH, sAL, sBH, sBL, wm, wn, lane, acc);

    #pragma unroll
    for (int mt = 0; mt < 4; mt++) {
        int i = itile * 128 + wm * 64 + mt * 16 + (lane >> 2);
        int n0 = ntile * 128 + wn * 32 + (lane & 3) * 2;
        #pragma unroll
        for (int nt = 0; nt < 4; nt++) {
            *(float2*)(g_T + (size_t)i * 4096 + n0 + nt * 8) =
                make_float2(acc[mt][nt][0], acc[mt][nt][1]);
            *(float2*)(g_T + (size_t)(i + 8) * 4096 + n0 + nt * 8) =
                make_float2(acc[mt][nt][2], acc[mt][nt][3]);
        }
    }
}

// ---------------------------------------------------------------------------
// bsplit: pre-build B fragments (hi/lo) of T_i for the pair GEMM.
// item t in [0,1024) per i: kt=t>>9, nt=(t>>5)&15, lane=t&31;
// p = nt*8+(lane>>2), f0 = kt*16+2*(lane&3); b0=(f0,f0+1), b1=(f0+8,f0+9)
// ---------------------------------------------------------------------------
__global__ __launch_bounds__(256) void bsplit_kernel()
{
    int i = blockIdx.x;
    const float* Ti = g_T + (size_t)i * 4096;
    uint2* dh = (uint2*)(g_Tbh + (size_t)i * 512);
    uint2* dl = (uint2*)(g_Tbl + (size_t)i * 512);
    #pragma unroll
    for (int k = 0; k < 4; k++) {
        int t = threadIdx.x + k * 256;
        int la = t & 31, nt = (t >> 5) & 15, kt = t >> 9;
        int p = nt * 8 + (la >> 2);
        int f0 = kt * 16 + (la & 3) * 2;
        float2 v0 = *(const float2*)(Ti + p * H + f0);
        float2 v1 = *(const float2*)(Ti + p * H + f0 + 8);
        uint32_t b0h, b0l, b1h, b1l;
        split_pair(v0.x, v0.y, b0h, b0l);
        split_pair(v1.x, v1.y, b1h, b1l);
        dh[t] = make_uint2(b0h, b1h);
        dl[t] = make_uint2(b0l, b1l);
    }
}

// ---------------------------------------------------------------------------
// pair: pair[i,j,p] = b3[p] + sum_f S2[j,f]*T[i,p,f].  CTA=(i, jtile).
// Pure copy fill (pre-split frags) + bf16x3 HMMA + direct stores.
// ---------------------------------------------------------------------------
__global__ __launch_bounds__(256) void pair_kernel(
    const float* __restrict__ b3, float* __restrict__ out)
{
    __shared__ uint4 sAH[512], sAL[512];
    __shared__ uint2 sBH[1024], sBL[1024];
    int tid = threadIdx.x, lane = tid & 31;
    int i = blockIdx.x, jtile = blockIdx.y;

    sAH[tid]       = g_Abh[jtile * 512 + tid];
    sAH[tid + 256] = g_Abh[jtile * 512 + tid + 256];
    sAL[tid]       = g_Abl[jtile * 512 + tid];
    sAL[tid + 256] = g_Abl[jtile * 512 + tid + 256];
    ((uint4*)sBH)[tid]       = g_Tbh[(size_t)i * 512 + tid];
    ((uint4*)sBH)[tid + 256] = g_Tbh[(size_t)i * 512 + tid + 256];
    ((uint4*)sBL)[tid]       = g_Tbl[(size_t)i * 512 + tid];
    ((uint4*)sBL)[tid + 256] = g_Tbl[(size_t)i * 512 + tid + 256];

    int wid = tid >> 5, wm = wid >> 2, wn = wid & 3;

    float acc[4][4][4];
    #pragma unroll
    for (int nt = 0; nt < 4; nt++) {
        float2 bv = __ldg((const float2*)(b3 + wn * 32 + nt * 8 + (lane & 3) * 2));
        #pragma unroll
        for (int mt = 0; mt < 4; mt++) {
            acc[mt][nt][0] = bv.x; acc[mt][nt][1] = bv.y;
            acc[mt][nt][2] = bv.x; acc[mt][nt][3] = bv.y;
        }
    }
    __syncthreads();

    gemm_compute(sAH, sAL, sBH, sBL, wm, wn, lane, acc);

    #pragma unroll
    for (int mt = 0; mt < 4; mt++) {
        int row = jtile * 128 + wm * 64 + mt * 16 + (lane >> 2);
        float* o0 = out + ((size_t)i * LSEQ + row) * P + wn * 32 + (lane & 3) * 2;
        #pragma unroll
        for (int nt = 0; nt < 4; nt++) {
            *(float2*)(o0 + nt * 8)         = make_float2(acc[mt][nt][0], acc[mt][nt][1]);
            *(float2*)(o0 + 8 * P + nt * 8) = make_float2(acc[mt][nt][2], acc[mt][nt][3]);
        }
    }
}

extern "C" void kernel_launch(void* const* d_in, const int* in_sizes, int n_in,
                              void* d_out, int out_size)
{
    const float* seq   = (const float*)d_in[0];
    const float* gamma = (const float*)d_in[1];
    const float* beta  = (const float*)d_in[2];
    const float* w1    = (const float*)d_in[3];
    const float* b1    = (const float*)d_in[4];
    const float* w2    = (const float*)d_in[5];
    const float* b2    = (const float*)d_in[6];
    const float* w3    = (const float*)d_in[7];
    const float* b3    = (const float*)d_in[8];

    ln_proj_kernel<<<LSEQ, 256>>>(seq, gamma, beta, w1, b1, w2, b2);
    asplit_kernel<<<12, 256>>>();
    tgemm_kernel<<<dim3(3, 32), 256>>>(w3);
    bsplit_kernel<<<LSEQ, 256>>>();
    pair_kernel<<<dim3(LSEQ, 3), 256>>>(b3, (float*)d_out);
}

// round 7
// speedup vs baseline: 1.8020x; 1.0829x over previous
#include <cuda_runtime.h>
#include <cuda_bf16.h>
#include <cstdint>

#define LSEQ 384
#define DSEQ 256
#define H    32
#define P    128

// ---------------------------------------------------------------------------
// scratch (__device__ globals; allocation-free rule)
// ---------------------------------------------------------------------------
__device__ float g_s1[LSEQ * H];
__device__ float g_s2[LSEQ * H];

// Pre-built m16n8k16 bf16 fragments (hi/lo planes for 3xBF16)
__device__ uint4 g_Abh[3 * 512],  g_Abl[3 * 512];   // S2  A-frags, per j-tile
__device__ uint4 g_As1h[3 * 512], g_As1l[3 * 512];  // s1  A-frags, per i-tile
__device__ uint4 g_Tbh[LSEQ * 512], g_Tbl[LSEQ * 512]; // T B-frags per i

// ---------------------------------------------------------------------------
// helpers
// ---------------------------------------------------------------------------
// bf16 split: h = packed bf16(x0)|bf16(x1), l = packed residuals
__device__ __forceinline__ void split_pair(float x0, float x1,
                                           uint32_t& h, uint32_t& l) {
    asm("cvt.rn.bf16x2.f32 %0, %1, %2;" : "=r"(h) : "f"(x1), "f"(x0));
    float r0 = x0 - __uint_as_float(h << 16);
    float r1 = x1 - __uint_as_float(h & 0xffff0000u);
    asm("cvt.rn.bf16x2.f32 %0, %1, %2;" : "=r"(l) : "f"(r1), "f"(r0));
}

__device__ __forceinline__ void mma_bf16(float* d, const uint4& a, const uint2& b) {
    asm("mma.sync.aligned.m16n8k16.row.col.f32.bf16.bf16.f32 "
        "{%0,%1,%2,%3},{%4,%5,%6,%7},{%8,%9},{%0,%1,%2,%3};"
        : "+f"(d[0]), "+f"(d[1]), "+f"(d[2]), "+f"(d[3])
        : "r"(a.x), "r"(a.y), "r"(a.z), "r"(a.w), "r"(b.x), "r"(b.y));
}

// shared 128x128 (K=32) bf16x3 mainloop: warp grid 2(m) x 4(n), warp tile 64x32
__device__ __forceinline__ void gemm_compute(
    const uint4* sAH, const uint4* sAL, const uint2* sBH, const uint2* sBL,
    int wm, int wn, int lane, float acc[4][4][4])
{
    #pragma unroll
    for (int kt = 0; kt < 2; kt++) {
        uint2 bh[4], bl[4];
        #pragma unroll
        for (int nt = 0; nt < 4; nt++) {
            int bi = (kt * 16 + wn * 4 + nt) * 32 + lane;
            bh[nt] = sBH[bi]; bl[nt] = sBL[bi];
        }
        #pragma unroll
        for (int mt = 0; mt < 4; mt++) {
            int ai = (kt * 8 + wm * 4 + mt) * 32 + lane;
            uint4 ah = sAH[ai], al = sAL[ai];
            #pragma unroll
            for (int nt = 0; nt < 4; nt++) {
                mma_bf16(acc[mt][nt], ah, bh[nt]);
                mma_bf16(acc[mt][nt], ah, bl[nt]);
                mma_bf16(acc[mt][nt], al, bh[nt]);
            }
        }
    }
}

// scatter one (hi,lo) frag word pair of T[i, p*32+f0 .. +1] into B-frag arrays
__device__ __forceinline__ void store_bfrag(int i, int n0, uint32_t h, uint32_t l) {
    int p = n0 >> 5, f0 = n0 & 31;
    int ktb = f0 >> 4, rr = f0 & 15;
    int comp = rr >> 3;                       // 0 -> b0 (.x), 1 -> b1 (.y)
    int la = (p & 7) * 4 + ((rr & 7) >> 1);
    int t = ktb * 512 + (p >> 3) * 32 + la;
    ((uint32_t*)g_Tbh)[(size_t)i * 2048 + t * 2 + comp] = h;
    ((uint32_t*)g_Tbl)[(size_t)i * 2048 + t * 2 + comp] = l;
}

// ---------------------------------------------------------------------------
// Kernel A: LayerNorm + two 256->32 projections. Block per row.
// ---------------------------------------------------------------------------
__global__ __launch_bounds__(256) void ln_proj_kernel(
    const float* __restrict__ seq,
    const float* __restrict__ gamma, const float* __restrict__ beta,
    const float* __restrict__ w1, const float* __restrict__ b1,
    const float* __restrict__ w2, const float* __restrict__ b2)
{
    int i = blockIdx.x;
    int t = threadIdx.x;
    __shared__ float xs[DSEQ];
    __shared__ float2 wred[8];

    float v = seq[i * DSEQ + t];
    float s = v, q = v * v;
    #pragma unroll
    for (int o = 16; o; o >>= 1) {
        s += __shfl_down_sync(0xffffffffu, s, o);
        q += __shfl_down_sync(0xffffffffu, q, o);
    }
    if ((t & 31) == 0) wred[t >> 5] = make_float2(s, q);
    __syncthreads();

    float ts = 0.f, tq = 0.f;
    #pragma unroll
    for (int k = 0; k < 8; k++) { ts += wred[k].x; tq += wred[k].y; }
    float mu   = ts * (1.f / DSEQ);
    float var  = tq * (1.f / DSEQ) - mu * mu;
    float rstd = rsqrtf(var + 1e-5f);

    xs[t] = (v - mu) * rstd * gamma[t] + beta[t];
    __syncthreads();

    int dot = t >> 2, quarter = t & 3;
    int which = dot >> 5, h = dot & 31;
    const float* W    = which ? w2 : w1;
    const float* bias = which ? b2 : b1;
    float* outp       = which ? g_s2 : g_s1;

    const float4* Wr = (const float4*)(W + h * DSEQ + quarter * 64);
    const float4* Xr = (const float4*)(xs + quarter * 64);
    float acc = 0.f;
    #pragma unroll
    for (int k = 0; k < 16; k++) {
        float4 a = __ldg(Wr + k);
        float4 x = Xr[k];
        acc += a.x * x.x + a.y * x.y + a.z * x.z + a.w * x.w;
    }
    acc += __shfl_down_sync(0xffffffffu, acc, 1);
    acc += __shfl_down_sync(0xffffffffu, acc, 2);
    if (quarter == 0) outp[i * H + h] = acc + bias[h];
}

// ---------------------------------------------------------------------------
// asplit: pre-build A fragments (hi/lo bf16) for S2 (first half) and s1 (second)
// ---------------------------------------------------------------------------
__global__ __launch_bounds__(256) void asplit_kernel()
{
    int gid = blockIdx.x * 256 + threadIdx.x;      // 0..3071
    int sel = gid >= 1536;
    int idx = sel ? gid - 1536 : gid;
    const float* src = sel ? g_s1 : g_s2;
    uint4* dh = sel ? g_As1h : g_Abh;
    uint4* dl = sel ? g_As1l : g_Abl;

    int lane = idx & 31, rest = idx >> 5;
    int mt = rest & 7, kt = (rest >> 3) & 1, tile = rest >> 4;
    int r = tile * 128 + mt * 16 + (lane >> 2);
    int c = kt * 16 + (lane & 3) * 2;

    float2 v00 = *(const float2*)(src + r * H + c);
    float2 v10 = *(const float2*)(src + (r + 8) * H + c);
    float2 v01 = *(const float2*)(src + r * H + c + 8);
    float2 v11 = *(const float2*)(src + (r + 8) * H + c + 8);
    uint4 hi, lo;
    split_pair(v00.x, v00.y, hi.x, lo.x);
    split_pair(v10.x, v10.y, hi.y, lo.y);
    split_pair(v01.x, v01.y, hi.z, lo.z);
    split_pair(v11.x, v11.y, hi.w, lo.w);
    dh[idx] = hi; dl[idx] = lo;
}

// ---------------------------------------------------------------------------
// tgemm: T[i, n] = sum_d s1[i,d]*w3[n>>5, d*32+(n&31)]  (M=384,N=4096,K=32)
// CTA = (itile, ntile), bf16x3 HMMA. Epilogue converts accumulators DIRECTLY
// into pair-GEMM B-fragments (no fp32 T materialization, no bsplit pass).
// ---------------------------------------------------------------------------
__global__ __launch_bounds__(256, 2) void tgemm_kernel(const float* __restrict__ w3)
{
    __shared__ uint4 sAH[512], sAL[512];
    __shared__ uint2 sBH[1024], sBL[1024];
    int tid = threadIdx.x, lane = tid & 31;
    int itile = blockIdx.x, ntile = blockIdx.y;

    sAH[tid]       = g_As1h[itile * 512 + tid];
    sAH[tid + 256] = g_As1h[itile * 512 + tid + 256];
    sAL[tid]       = g_As1l[itile * 512 + tid];
    sAL[tid + 256] = g_As1l[itile * 512 + tid + 256];

    #pragma unroll
    for (int k = 0; k < 4; k++) {
        int t = tid + k * 256;                      // 0..1023
        int la = t & 31, nt = (t >> 5) & 15, kt = t >> 9;
        int n = ntile * 128 + nt * 8 + (la >> 2);
        int p = n >> 5, f = n & 31;
        int d0 = kt * 16 + (la & 3) * 2;
        const float* wp = w3 + p * (H * H);
        float v00 = __ldg(wp + d0 * H + f);
        float v01 = __ldg(wp + (d0 + 1) * H + f);
        float v10 = __ldg(wp + (d0 + 8) * H + f);
        float v11 = __ldg(wp + (d0 + 9) * H + f);
        uint32_t b0h, b0l, b1h, b1l;
        split_pair(v00, v01, b0h, b0l);
        split_pair(v10, v11, b1h, b1l);
        sBH[t] = make_uint2(b0h, b1h);
        sBL[t] = make_uint2(b0l, b1l);
    }

    float acc[4][4][4];
    #pragma unroll
    for (int a = 0; a < 4; a++)
        #pragma unroll
        for (int b = 0; b < 4; b++)
            #pragma unroll
            for (int c = 0; c < 4; c++) acc[a][b][c] = 0.f;
    __syncthreads();

    int wid = tid >> 5, wm = wid >> 2, wn = wid & 3;
    gemm_compute(sAH, sAL, sBH, sBL, wm, wn, lane, acc);

    #pragma unroll
    for (int mt = 0; mt < 4; mt++) {
        int i = itile * 128 + wm * 64 + mt * 16 + (lane >> 2);
        int n0 = ntile * 128 + wn * 32 + (lane & 3) * 2;
        #pragma unroll
        for (int nt = 0; nt < 4; nt++) {
            uint32_t h, l;
            split_pair(acc[mt][nt][0], acc[mt][nt][1], h, l);
            store_bfrag(i, n0 + nt * 8, h, l);
            split_pair(acc[mt][nt][2], acc[mt][nt][3], h, l);
            store_bfrag(i + 8, n0 + nt * 8, h, l);
        }
    }
}

// ---------------------------------------------------------------------------
// pair: pair[i,j,p] = b3[p] + sum_f S2[j,f]*T[i,p,f].  CTA=(i, jtile).
// Pure copy fill (pre-split frags) + bf16x3 HMMA + direct stores.
// ---------------------------------------------------------------------------
__global__ __launch_bounds__(256, 2) void pair_kernel(
    const float* __restrict__ b3, float* __restrict__ out)
{
    __shared__ uint4 sAH[512], sAL[512];
    __shared__ uint2 sBH[1024], sBL[1024];
    int tid = threadIdx.x, lane = tid & 31;
    int i = blockIdx.x, jtile = blockIdx.y;

    sAH[tid]       = g_Abh[jtile * 512 + tid];
    sAH[tid + 256] = g_Abh[jtile * 512 + tid + 256];
    sAL[tid]       = g_Abl[jtile * 512 + tid];
    sAL[tid + 256] = g_Abl[jtile * 512 + tid + 256];
    ((uint4*)sBH)[tid]       = g_Tbh[(size_t)i * 512 + tid];
    ((uint4*)sBH)[tid + 256] = g_Tbh[(size_t)i * 512 + tid + 256];
    ((uint4*)sBL)[tid]       = g_Tbl[(size_t)i * 512 + tid];
    ((uint4*)sBL)[tid + 256] = g_Tbl[(size_t)i * 512 + tid + 256];

    int wid = tid >> 5, wm = wid >> 2, wn = wid & 3;

    float acc[4][4][4];
    #pragma unroll
    for (int nt = 0; nt < 4; nt++) {
        float2 bv = __ldg((const float2*)(b3 + wn * 32 + nt * 8 + (lane & 3) * 2));
        #pragma unroll
        for (int mt = 0; mt < 4; mt++) {
            acc[mt][nt][0] = bv.x; acc[mt][nt][1] = bv.y;
            acc[mt][nt][2] = bv.x; acc[mt][nt][3] = bv.y;
        }
    }
    __syncthreads();

    gemm_compute(sAH, sAL, sBH, sBL, wm, wn, lane, acc);

    #pragma unroll
    for (int mt = 0; mt < 4; mt++) {
        int row = jtile * 128 + wm * 64 + mt * 16 + (lane >> 2);
        float* o0 = out + ((size_t)i * LSEQ + row) * P + wn * 32 + (lane & 3) * 2;
        #pragma unroll
        for (int nt = 0; nt < 4; nt++) {
            *(float2*)(o0 + nt * 8)         = make_float2(acc[mt][nt][0], acc[mt][nt][1]);
            *(float2*)(o0 + 8 * P + nt * 8) = make_float2(acc[mt][nt][2], acc[mt][nt][3]);
        }
    }
}

extern "C" void kernel_launch(void* const* d_in, const int* in_sizes, int n_in,
                              void* d_out, int out_size)
{
    const float* seq   = (const float*)d_in[0];
    const float* gamma = (const float*)d_in[1];
    const float* beta  = (const float*)d_in[2];
    const float* w1    = (const float*)d_in[3];
    const float* b1    = (const float*)d_in[4];
    const float* w2    = (const float*)d_in[5];
    const float* b2    = (const float*)d_in[6];
    const float* w3    = (const float*)d_in[7];
    const float* b3    = (const float*)d_in[8];

    ln_proj_kernel<<<LSEQ, 256>>>(seq, gamma, beta, w1, b1, w2, b2);
    asplit_kernel<<<12, 256>>>();
    tgemm_kernel<<<dim3(3, 32), 256>>>(w3);
    pair_kernel<<<dim3(LSEQ, 3), 256>>>(b3, (float*)d_out);
}

// round 9
// speedup vs baseline: 1.9230x; 1.0672x over previous
#include <cuda_runtime.h>
#include <cuda_bf16.h>
#include <cstdint>

#define LSEQ 384
#define DSEQ 256
#define H    32
#define P    128

// ---------------------------------------------------------------------------
// scratch (__device__ globals; allocation-free rule)
// ---------------------------------------------------------------------------
__device__ float g_s1[LSEQ * H];
__device__ float g_s2[LSEQ * H];

// Pre-built m16n8k16 bf16 fragments (hi/lo planes for 3xBF16)
__device__ uint4 g_Abh[3 * 512],  g_Abl[3 * 512];   // S2  A-frags, per j-tile
__device__ uint4 g_As1h[3 * 512], g_As1l[3 * 512];  // s1  A-frags, per i-tile
__device__ uint4 g_Tbh[LSEQ * 512], g_Tbl[LSEQ * 512]; // T B-frags per i

// ---------------------------------------------------------------------------
// helpers
// ---------------------------------------------------------------------------
__device__ __forceinline__ uint32_t smem_u32(const void* p) {
    uint32_t a;
    asm("{ .reg .u64 t; cvta.to.shared.u64 t, %1; cvt.u32.u64 %0, t; }"
        : "=r"(a) : "l"(p));
    return a;
}
__device__ __forceinline__ void cp16(uint32_t dst, const void* src) {
    asm volatile("cp.async.cg.shared.global [%0], [%1], 16;"
                 :: "r"(dst), "l"(src));
}
#define CP_COMMIT() asm volatile("cp.async.commit_group;" ::: "memory")

// bf16 split: h = packed bf16(x0)|bf16(x1), l = packed residuals
__device__ __forceinline__ void split_pair(float x0, float x1,
                                           uint32_t& h, uint32_t& l) {
    asm("cvt.rn.bf16x2.f32 %0, %1, %2;" : "=r"(h) : "f"(x1), "f"(x0));
    float r0 = x0 - __uint_as_float(h << 16);
    float r1 = x1 - __uint_as_float(h & 0xffff0000u);
    asm("cvt.rn.bf16x2.f32 %0, %1, %2;" : "=r"(l) : "f"(r1), "f"(r0));
}

__device__ __forceinline__ void mma_bf16(float* d, const uint4& a, const uint2& b) {
    asm("mma.sync.aligned.m16n8k16.row.col.f32.bf16.bf16.f32 "
        "{%0,%1,%2,%3},{%4,%5,%6,%7},{%8,%9},{%0,%1,%2,%3};"
        : "+f"(d[0]), "+f"(d[1]), "+f"(d[2]), "+f"(d[3])
        : "r"(a.x), "r"(a.y), "r"(a.z), "r"(a.w), "r"(b.x), "r"(b.y));
}

// 128 x (NT*32) (K=32) bf16x3 mainloop: warp grid 2(m) x 4(n)
template<int NT>
__device__ __forceinline__ void gemm_compute(
    const uint4* sAH, const uint4* sAL, const uint2* sBH, const uint2* sBL,
    int wm, int wn, int lane, float acc[4][NT][4])
{
    #pragma unroll
    for (int kt = 0; kt < 2; kt++) {
        uint2 bh[NT], bl[NT];
        #pragma unroll
        for (int nt = 0; nt < NT; nt++) {
            int bi = (kt * 4 * NT + wn * NT + nt) * 32 + lane;
            bh[nt] = sBH[bi]; bl[nt] = sBL[bi];
        }
        #pragma unroll
        for (int mt = 0; mt < 4; mt++) {
            int ai = (kt * 8 + wm * 4 + mt) * 32 + lane;
            uint4 ah = sAH[ai], al = sAL[ai];
            #pragma unroll
            for (int nt = 0; nt < NT; nt++) {
                mma_bf16(acc[mt][nt], ah, bh[nt]);
                mma_bf16(acc[mt][nt], ah, bl[nt]);
                mma_bf16(acc[mt][nt], al, bh[nt]);
            }
        }
    }
}

// scatter one (hi,lo) frag word pair of T[i, p*32+f0 .. +1] into B-frag arrays
__device__ __forceinline__ void store_bfrag(int i, int n0, uint32_t h, uint32_t l) {
    int p = n0 >> 5, f0 = n0 & 31;
    int ktb = f0 >> 4, rr = f0 & 15;
    int comp = rr >> 3;
    int la = (p & 7) * 4 + ((rr & 7) >> 1);
    int t = ktb * 512 + (p >> 3) * 32 + la;
    ((uint32_t*)g_Tbh)[(size_t)i * 2048 + t * 2 + comp] = h;
    ((uint32_t*)g_Tbl)[(size_t)i * 2048 + t * 2 + comp] = l;
}

// ---------------------------------------------------------------------------
// Kernel A: LayerNorm + two 256->32 projections. Block per row.
// ---------------------------------------------------------------------------
__global__ __launch_bounds__(256) void ln_proj_kernel(
    const float* __restrict__ seq,
    const float* __restrict__ gamma, const float* __restrict__ beta,
    const float* __restrict__ w1, const float* __restrict__ b1,
    const float* __restrict__ w2, const float* __restrict__ b2)
{
    int i = blockIdx.x;
    int t = threadIdx.x;
    __shared__ float xs[DSEQ];
    __shared__ float2 wred[8];

    float v = seq[i * DSEQ + t];
    float s = v, q = v * v;
    #pragma unroll
    for (int o = 16; o; o >>= 1) {
        s += __shfl_down_sync(0xffffffffu, s, o);
        q += __shfl_down_sync(0xffffffffu, q, o);
    }
    if ((t & 31) == 0) wred[t >> 5] = make_float2(s, q);
    __syncthreads();

    float ts = 0.f, tq = 0.f;
    #pragma unroll
    for (int k = 0; k < 8; k++) { ts += wred[k].x; tq += wred[k].y; }
    float mu   = ts * (1.f / DSEQ);
    float var  = tq * (1.f / DSEQ) - mu * mu;
    float rstd = rsqrtf(var + 1e-5f);

    xs[t] = (v - mu) * rstd * gamma[t] + beta[t];
    __syncthreads();

    int dot = t >> 2, quarter = t & 3;
    int which = dot >> 5, h = dot & 31;
    const float* W    = which ? w2 : w1;
    const float* bias = which ? b2 : b1;
    float* outp       = which ? g_s2 : g_s1;

    const float4* Wr = (const float4*)(W + h * DSEQ + quarter * 64);
    const float4* Xr = (const float4*)(xs + quarter * 64);
    float acc = 0.f;
    #pragma unroll
    for (int k = 0; k < 16; k++) {
        float4 a = __ldg(Wr + k);
        float4 x = Xr[k];
        acc += a.x * x.x + a.y * x.y + a.z * x.z + a.w * x.w;
    }
    acc += __shfl_down_sync(0xffffffffu, acc, 1);
    acc += __shfl_down_sync(0xffffffffu, acc, 2);
    if (quarter == 0) outp[i * H + h] = acc + bias[h];
}

// ---------------------------------------------------------------------------
// asplit: pre-build A fragments (hi/lo bf16) for S2 (first half) and s1 (second)
// ---------------------------------------------------------------------------
__global__ __launch_bounds__(256) void asplit_kernel()
{
    int gid = blockIdx.x * 256 + threadIdx.x;      // 0..3071
    int sel = gid >= 1536;
    int idx = sel ? gid - 1536 : gid;
    const float* src = sel ? g_s1 : g_s2;
    uint4* dh = sel ? g_As1h : g_Abh;
    uint4* dl = sel ? g_As1l : g_Abl;

    int lane = idx & 31, rest = idx >> 5;
    int mt = rest & 7, kt = (rest >> 3) & 1, tile = rest >> 4;
    int r = tile * 128 + mt * 16 + (lane >> 2);
    int c = kt * 16 + (lane & 3) * 2;

    float2 v00 = *(const float2*)(src + r * H + c);
    float2 v10 = *(const float2*)(src + (r + 8) * H + c);
    float2 v01 = *(const float2*)(src + r * H + c + 8);
    float2 v11 = *(const float2*)(src + (r + 8) * H + c + 8);
    uint4 hi, lo;
    split_pair(v00.x, v00.y, hi.x, lo.x);
    split_pair(v10.x, v10.y, hi.y, lo.y);
    split_pair(v01.x, v01.y, hi.z, lo.z);
    split_pair(v11.x, v11.y, hi.w, lo.w);
    dh[idx] = hi; dl[idx] = lo;
}

// ---------------------------------------------------------------------------
// tgemm: T[i, n] = sum_d s1[i,d]*w3[n>>5, d*32+(n&31)]  (M=384, N=4096, K=32)
// CTA = (itile, ntile64): 128x64 tile, grid (3,64)=192. w3 slice staged into
// SMEM coalesced first; epilogue writes pair-GEMM B-fragments directly.
// ---------------------------------------------------------------------------
__global__ __launch_bounds__(256) void tgemm_kernel(const float* __restrict__ w3)
{
    __shared__ float ws[2048];                  // 8 KB w3 slice (2 p-rows)
    __shared__ uint4 sAH[512], sAL[512];        // 16 KB A frags
    __shared__ uint2 sBH[512], sBL[512];        // 8 KB B frags
    int tid = threadIdx.x, lane = tid & 31;
    int itile = blockIdx.x, ntile = blockIdx.y;

    // stage w3 slice coalesced: p in [ntile*2, ntile*2+2), 2048 floats
    const float4* wsrc = (const float4*)(w3 + (size_t)ntile * 2 * (H * H));
    float4* wdst = (float4*)ws;
    wdst[tid]       = __ldg(wsrc + tid);
    wdst[tid + 256] = __ldg(wsrc + tid + 256);

    sAH[tid]       = g_As1h[itile * 512 + tid];
    sAH[tid + 256] = g_As1h[itile * 512 + tid + 256];
    sAL[tid]       = g_As1l[itile * 512 + tid];
    sAL[tid + 256] = g_As1l[itile * 512 + tid + 256];
    __syncthreads();

    // build B frags from staged w3 (512 items, 2 per thread)
    #pragma unroll
    for (int k = 0; k < 2; k++) {
        int t = tid + k * 256;
        int la = t & 31, nt8 = (t >> 5) & 7, kt = t >> 8;
        int nl = nt8 * 8 + (la >> 2);           // 0..63 local n
        int pl = nl >> 5, f = nl & 31;
        int d0 = kt * 16 + (la & 3) * 2;
        const float* wp = ws + pl * 1024;
        float v00 = wp[d0 * H + f];
        float v01 = wp[(d0 + 1) * H + f];
        float v10 = wp[(d0 + 8) * H + f];
        float v11 = wp[(d0 + 9) * H + f];
        uint32_t b0h, b0l, b1h, b1l;
        split_pair(v00, v01, b0h, b0l);
        split_pair(v10, v11, b1h, b1l);
        sBH[t] = make_uint2(b0h, b1h);
        sBL[t] = make_uint2(b0l, b1l);
    }

    float acc[4][2][4];
    #pragma unroll
    for (int a = 0; a < 4; a++)
        #pragma unroll
        for (int b = 0; b < 2; b++)
            #pragma unroll
            for (int c = 0; c < 4; c++) acc[a][b][c] = 0.f;
    __syncthreads();

    int wid = tid >> 5, wm = wid >> 2, wn = wid & 3;
    gemm_compute<2>(sAH, sAL, sBH, sBL, wm, wn, lane, acc);

    #pragma unroll
    for (int mt = 0; mt < 4; mt++) {
        int i = itile * 128 + wm * 64 + mt * 16 + (lane >> 2);
        int n0 = ntile * 64 + wn * 16 + (lane & 3) * 2;
        #pragma unroll
        for (int nt = 0; nt < 2; nt++) {
            uint32_t h, l;
            split_pair(acc[mt][nt][0], acc[mt][nt][1], h, l);
            store_bfrag(i, n0 + nt * 8, h, l);
            split_pair(acc[mt][nt][2], acc[mt][nt][3], h, l);
            store_bfrag(i + 8, n0 + nt * 8, h, l);
        }
    }
}

// ---------------------------------------------------------------------------
// pair: pair[i,j,p] = b3[p] + sum_f S2[j,f]*T[i,p,f].
// CTA = (i-quad, jtile): grid 96x3 = 288 ~ one wave at 2 CTAs/SM.
// SMEM: B frags for 4 i's (4 x 16 KB) + A frags for jtile (16 KB) = 80 KB,
// filled with cp.async in 4 commit-groups; tile t waits group t then
// computes + stores while later B tiles stream in.
// ---------------------------------------------------------------------------
#define PAIR_SMEM 81920

__global__ __launch_bounds__(256, 2) void pair_kernel(
    const float* __restrict__ b3, float* __restrict__ out)
{
    extern __shared__ __align__(16) char ps[];
    int tid = threadIdx.x, lane = tid & 31, wid = tid >> 5;
    int wm = wid >> 2, wn = wid & 3;
    int iq = blockIdx.x, jt = blockIdx.y;
    int i0 = iq * 4;
    uint32_t sb = smem_u32(ps);

    // A frags (16 KB @ 65536): hi then lo
    cp16(sb + 65536 + tid * 16,        &g_Abh[jt * 512 + tid]);
    cp16(sb + 65536 + (tid+256) * 16,  &g_Abh[jt * 512 + tid + 256]);
    cp16(sb + 73728 + tid * 16,        &g_Abl[jt * 512 + tid]);
    cp16(sb + 73728 + (tid+256) * 16,  &g_Abl[jt * 512 + tid + 256]);
    // B frags for 4 i's, one commit-group each (group0 also covers A)
    #pragma unroll
    for (int it = 0; it < 4; it++) {
        uint32_t base = sb + it * 16384;
        cp16(base + tid * 16,               &g_Tbh[(size_t)(i0+it) * 512 + tid]);
        cp16(base + (tid+256) * 16,         &g_Tbh[(size_t)(i0+it) * 512 + tid + 256]);
        cp16(base + 8192 + tid * 16,        &g_Tbl[(size_t)(i0+it) * 512 + tid]);
        cp16(base + 8192 + (tid+256) * 16,  &g_Tbl[(size_t)(i0+it) * 512 + tid + 256]);
        CP_COMMIT();
    }

    float2 bv[4];
    #pragma unroll
    for (int nt = 0; nt < 4; nt++)
        bv[nt] = __ldg((const float2*)(b3 + wn * 32 + nt * 8 + (lane & 3) * 2));

    const uint4* sAH = (const uint4*)(ps + 65536);
    const uint4* sAL = (const uint4*)(ps + 73728);

    #pragma unroll
    for (int it = 0; it < 4; it++) {
        if      (it == 0) asm volatile("cp.async.wait_group 3;" ::: "memory");
        else if (it == 1) asm volatile("cp.async.wait_group 2;" ::: "memory");
        else if (it == 2) asm volatile("cp.async.wait_group 1;" ::: "memory");
        else              asm volatile("cp.async.wait_group 0;" ::: "memory");
        __syncthreads();

        float acc[4][4][4];
        #pragma unroll
        for (int nt = 0; nt < 4; nt++)
            #pragma unroll
            for (int mt = 0; mt < 4; mt++) {
                acc[mt][nt][0] = bv[nt].x; acc[mt][nt][1] = bv[nt].y;
                acc[mt][nt][2] = bv[nt].x; acc[mt][nt][3] = bv[nt].y;
            }

        const uint2* sBH = (const uint2*)(ps + it * 16384);
        const uint2* sBL = (const uint2*)(ps + it * 16384 + 8192);
        gemm_compute<4>(sAH, sAL, sBH, sBL, wm, wn, lane, acc);

        #pragma unroll
        for (int mt = 0; mt < 4; mt++) {
            int row = jt * 128 + wm * 64 + mt * 16 + (lane >> 2);
            float* o0 = out + ((size_t)(i0 + it) * LSEQ + row) * P
                            + wn * 32 + (lane & 3) * 2;
            #pragma unroll
            for (int nt = 0; nt < 4; nt++) {
                *(float2*)(o0 + nt * 8)         = make_float2(acc[mt][nt][0], acc[mt][nt][1]);
                *(float2*)(o0 + 8 * P + nt * 8) = make_float2(acc[mt][nt][2], acc[mt][nt][3]);
            }
        }
    }
}

extern "C" void kernel_launch(void* const* d_in, const int* in_sizes, int n_in,
                              void* d_out, int out_size)
{
    const float* seq   = (const float*)d_in[0];
    const float* gamma = (const float*)d_in[1];
    const float* beta  = (const float*)d_in[2];
    const float* w1    = (const float*)d_in[3];
    const float* b1    = (const float*)d_in[4];
    const float* w2    = (const float*)d_in[5];
    const float* b2    = (const float*)d_in[6];
    const float* w3    = (const float*)d_in[7];
    const float* b3    = (const float*)d_in[8];

    cudaFuncSetAttribute(pair_kernel,
                         cudaFuncAttributeMaxDynamicSharedMemorySize, PAIR_SMEM);

    ln_proj_kernel<<<LSEQ, 256>>>(seq, gamma, beta, w1, b1, w2, b2);
    asplit_kernel<<<12, 256>>>();
    tgemm_kernel<<<dim3(3, 64), 256>>>(w3);
    pair_kernel<<<dim3(96, 3), 256, PAIR_SMEM>>>(b3, (float*)d_out);
}

// round 10
// speedup vs baseline: 2.1268x; 1.1060x over previous
#include <cuda_runtime.h>
#include <cuda_bf16.h>
#include <cstdint>

#define LSEQ 384
#define DSEQ 256
#define H    32
#define P    128

// ---------------------------------------------------------------------------
// scratch (__device__ globals; allocation-free rule)
// ---------------------------------------------------------------------------
__device__ float g_s1[LSEQ * H];
__device__ float g_s2[LSEQ * H];

// A fragments (hi/lo planes), m16n8k16 layout
__device__ uint4 g_Abh[3 * 512],  g_Abl[3 * 512];   // S2  A-frags, per j-tile
__device__ uint4 g_As1h[3 * 512], g_As1l[3 * 512];  // s1  A-frags, per i-tile
// T B-fragments, interleaved {b0h, b1h, b0l, b1l} per slot, 1024 slots (16KB)/i
__device__ uint4 g_Tb[(size_t)LSEQ * 1024];

// ---------------------------------------------------------------------------
// helpers
// ---------------------------------------------------------------------------
__device__ __forceinline__ uint32_t smem_u32(const void* p) {
    uint32_t a;
    asm("{ .reg .u64 t; cvta.to.shared.u64 t, %1; cvt.u32.u64 %0, t; }"
        : "=r"(a) : "l"(p));
    return a;
}
__device__ __forceinline__ void cp16(uint32_t dst, const void* src) {
    asm volatile("cp.async.cg.shared.global [%0], [%1], 16;"
                 :: "r"(dst), "l"(src));
}
#define CP_COMMIT() asm volatile("cp.async.commit_group;" ::: "memory")

// bf16 split: h = packed bf16(x0)|bf16(x1), l = packed residuals
__device__ __forceinline__ void split_pair(float x0, float x1,
                                           uint32_t& h, uint32_t& l) {
    asm("cvt.rn.bf16x2.f32 %0, %1, %2;" : "=r"(h) : "f"(x1), "f"(x0));
    float r0 = x0 - __uint_as_float(h << 16);
    float r1 = x1 - __uint_as_float(h & 0xffff0000u);
    asm("cvt.rn.bf16x2.f32 %0, %1, %2;" : "=r"(l) : "f"(r1), "f"(r0));
}

__device__ __forceinline__ void mma_bf16(float* d, const uint4& a, const uint2& b) {
    asm("mma.sync.aligned.m16n8k16.row.col.f32.bf16.bf16.f32 "
        "{%0,%1,%2,%3},{%4,%5,%6,%7},{%8,%9},{%0,%1,%2,%3};"
        : "+f"(d[0]), "+f"(d[1]), "+f"(d[2]), "+f"(d[3])
        : "r"(a.x), "r"(a.y), "r"(a.z), "r"(a.w), "r"(b.x), "r"(b.y));
}

// 128 x (NT*32) (K=32) bf16x3 mainloop; B slots interleaved {b0h,b1h,b0l,b1l}
template<int NT>
__device__ __forceinline__ void gemm_compute(
    const uint4* sAH, const uint4* sAL, const uint4* sB,
    int wm, int wn, int lane, float acc[4][NT][4])
{
    #pragma unroll
    for (int kt = 0; kt < 2; kt++) {
        uint2 bh[NT], bl[NT];
        #pragma unroll
        for (int nt = 0; nt < NT; nt++) {
            uint4 v = sB[(kt * 4 * NT + wn * NT + nt) * 32 + lane];
            bh[nt] = make_uint2(v.x, v.y);
            bl[nt] = make_uint2(v.z, v.w);
        }
        #pragma unroll
        for (int mt = 0; mt < 4; mt++) {
            int ai = (kt * 8 + wm * 4 + mt) * 32 + lane;
            uint4 ah = sAH[ai], al = sAL[ai];
            #pragma unroll
            for (int nt = 0; nt < NT; nt++) {
                mma_bf16(acc[mt][nt], ah, bh[nt]);
                mma_bf16(acc[mt][nt], ah, bl[nt]);
                mma_bf16(acc[mt][nt], al, bh[nt]);
            }
        }
    }
}

// Fragment slot for pair-GEMM B, PERMUTED p mapping:
//   p = wn*32 + (nt>>1)*16 + (j>>1)*4 + (nt&1)*2 + (j&1)
// slot t = (ktb*16 + wn*4 + nt)*32 + j*4 + kpair,  ktb = f0>>4, kpair=(f0>>1)&3
__device__ __forceinline__ int bfrag_slot(int p, int f0) {
    int g = p & 31, wnp = p >> 5;
    int ntp = ((g >> 4) & 1) * 2 + ((g >> 1) & 1);
    int j   = ((g >> 2) & 3) * 2 + (g & 1);
    return ((f0 >> 4) * 16 + wnp * 4 + ntp) * 32 + j * 4 + ((f0 >> 1) & 3);
}

// ---------------------------------------------------------------------------
// Kernel A: LayerNorm + two 256->32 projections. Block per row.
// ---------------------------------------------------------------------------
__global__ __launch_bounds__(256) void ln_proj_kernel(
    const float* __restrict__ seq,
    const float* __restrict__ gamma, const float* __restrict__ beta,
    const float* __restrict__ w1, const float* __restrict__ b1,
    const float* __restrict__ w2, const float* __restrict__ b2)
{
    int i = blockIdx.x;
    int t = threadIdx.x;
    __shared__ float xs[DSEQ];
    __shared__ float2 wred[8];

    float v = seq[i * DSEQ + t];
    float s = v, q = v * v;
    #pragma unroll
    for (int o = 16; o; o >>= 1) {
        s += __shfl_down_sync(0xffffffffu, s, o);
        q += __shfl_down_sync(0xffffffffu, q, o);
    }
    if ((t & 31) == 0) wred[t >> 5] = make_float2(s, q);
    __syncthreads();

    float ts = 0.f, tq = 0.f;
    #pragma unroll
    for (int k = 0; k < 8; k++) { ts += wred[k].x; tq += wred[k].y; }
    float mu   = ts * (1.f / DSEQ);
    float var  = tq * (1.f / DSEQ) - mu * mu;
    float rstd = rsqrtf(var + 1e-5f);

    xs[t] = (v - mu) * rstd * gamma[t] + beta[t];
    __syncthreads();

    int dot = t >> 2, quarter = t & 3;
    int which = dot >> 5, h = dot & 31;
    const float* W    = which ? w2 : w1;
    const float* bias = which ? b2 : b1;
    float* outp       = which ? g_s2 : g_s1;

    const float4* Wr = (const float4*)(W + h * DSEQ + quarter * 64);
    const float4* Xr = (const float4*)(xs + quarter * 64);
    float acc = 0.f;
    #pragma unroll
    for (int k = 0; k < 16; k++) {
        float4 a = __ldg(Wr + k);
        float4 x = Xr[k];
        acc += a.x * x.x + a.y * x.y + a.z * x.z + a.w * x.w;
    }
    acc += __shfl_down_sync(0xffffffffu, acc, 1);
    acc += __shfl_down_sync(0xffffffffu, acc, 2);
    if (quarter == 0) outp[i * H + h] = acc + bias[h];
}

// ---------------------------------------------------------------------------
// asplit: pre-build A fragments (hi/lo bf16) for S2 (first half) and s1 (second)
// ---------------------------------------------------------------------------
__global__ __launch_bounds__(256) void asplit_kernel()
{
    int gid = blockIdx.x * 256 + threadIdx.x;      // 0..3071
    int sel = gid >= 1536;
    int idx = sel ? gid - 1536 : gid;
    const float* src = sel ? g_s1 : g_s2;
    uint4* dh = sel ? g_As1h : g_Abh;
    uint4* dl = sel ? g_As1l : g_Abl;

    int lane = idx & 31, rest = idx >> 5;
    int mt = rest & 7, kt = (rest >> 3) & 1, tile = rest >> 4;
    int r = tile * 128 + mt * 16 + (lane >> 2);
    int c = kt * 16 + (lane & 3) * 2;

    float2 v00 = *(const float2*)(src + r * H + c);
    float2 v10 = *(const float2*)(src + (r + 8) * H + c);
    float2 v01 = *(const float2*)(src + r * H + c + 8);
    float2 v11 = *(const float2*)(src + (r + 8) * H + c + 8);
    uint4 hi, lo;
    split_pair(v00.x, v00.y, hi.x, lo.x);
    split_pair(v10.x, v10.y, hi.y, lo.y);
    split_pair(v01.x, v01.y, hi.z, lo.z);
    split_pair(v11.x, v11.y, hi.w, lo.w);
    dh[idx] = hi; dl[idx] = lo;
}

// ---------------------------------------------------------------------------
// tgemm: T[i, n] = sum_d s1[i,d]*w3[n>>5, d*32+(n&31)]  (M=384, N=4096, K=32)
// CTA = (itile, ntile64): 128x64 tile, grid (3,64)=192. Epilogue packs each
// (b0,b1) pair of the pair-GEMM B-fragments as ONE aligned uint4 store.
// ---------------------------------------------------------------------------
__global__ __launch_bounds__(256) void tgemm_kernel(const float* __restrict__ w3)
{
    __shared__ float ws[2048];                  // 8 KB w3 slice (2 p-rows)
    __shared__ uint4 sAH[512], sAL[512];        // 16 KB A frags
    __shared__ uint4 sB[512];                   // 8 KB B frags (interleaved)
    int tid = threadIdx.x, lane = tid & 31;
    int itile = blockIdx.x, ntile = blockIdx.y;

    const float4* wsrc = (const float4*)(w3 + (size_t)ntile * 2 * (H * H));
    float4* wdst = (float4*)ws;
    wdst[tid]       = __ldg(wsrc + tid);
    wdst[tid + 256] = __ldg(wsrc + tid + 256);

    sAH[tid]       = g_As1h[itile * 512 + tid];
    sAH[tid + 256] = g_As1h[itile * 512 + tid + 256];
    sAL[tid]       = g_As1l[itile * 512 + tid];
    sAL[tid + 256] = g_As1l[itile * 512 + tid + 256];
    __syncthreads();

    #pragma unroll
    for (int k = 0; k < 2; k++) {
        int t = tid + k * 256;
        int la = t & 31, nt8 = (t >> 5) & 7, kt = t >> 8;
        int nl = nt8 * 8 + (la >> 2);
        int pl = nl >> 5, f = nl & 31;
        int d0 = kt * 16 + (la & 3) * 2;
        const float* wp = ws + pl * 1024;
        float v00 = wp[d0 * H + f];
        float v01 = wp[(d0 + 1) * H + f];
        float v10 = wp[(d0 + 8) * H + f];
        float v11 = wp[(d0 + 9) * H + f];
        uint32_t b0h, b0l, b1h, b1l;
        split_pair(v00, v01, b0h, b0l);
        split_pair(v10, v11, b1h, b1l);
        sB[t] = make_uint4(b0h, b1h, b0l, b1l);
    }

    float acc[4][2][4];
    #pragma unroll
    for (int a = 0; a < 4; a++)
        #pragma unroll
        for (int b = 0; b < 2; b++)
            #pragma unroll
            for (int c = 0; c < 4; c++) acc[a][b][c] = 0.f;
    __syncthreads();

    int wid = tid >> 5, wm = wid >> 2, wn = wid & 3;
    gemm_compute<2>(sAH, sAL, sB, wm, wn, lane, acc);

    // epilogue: nt=0 gives (f0,f0+1)=b0, nt=1 gives (f0+8,f0+9)=b1 (same p)
    int n_base = ntile * 64 + wn * 16 + (lane & 3) * 2;
    int pg = n_base >> 5, f0 = n_base & 31;
    int slot = bfrag_slot(pg, f0);
    #pragma unroll
    for (int mt = 0; mt < 4; mt++) {
        int i = itile * 128 + wm * 64 + mt * 16 + (lane >> 2);
        uint32_t b0h, b0l, b1h, b1l;
        split_pair(acc[mt][0][0], acc[mt][0][1], b0h, b0l);
        split_pair(acc[mt][1][0], acc[mt][1][1], b1h, b1l);
        g_Tb[(size_t)i * 1024 + slot] = make_uint4(b0h, b1h, b0l, b1l);
        split_pair(acc[mt][0][2], acc[mt][0][3], b0h, b0l);
        split_pair(acc[mt][1][2], acc[mt][1][3], b1h, b1l);
        g_Tb[(size_t)(i + 8) * 1024 + slot] = make_uint4(b0h, b1h, b0l, b1l);
    }
}

// ---------------------------------------------------------------------------
// pair: pair[i,j,p] = b3[p] + sum_f S2[j,f]*T[i,p,f].
// CTA = (i-quad, jtile): grid 96x3 = 288 ~ one wave at 2 CTAs/SM.
// Permuted p mapping makes each thread's output 4+4 contiguous floats:
// 16 STG.128 per tile, each 8 rows x 64B contiguous.
// ---------------------------------------------------------------------------
#define PAIR_SMEM 81920

__global__ __launch_bounds__(256, 2) void pair_kernel(
    const float* __restrict__ b3, float* __restrict__ out)
{
    extern __shared__ __align__(16) char ps[];
    int tid = threadIdx.x, lane = tid & 31, wid = tid >> 5;
    int wm = wid >> 2, wn = wid & 3, q = lane & 3;
    int iq = blockIdx.x, jt = blockIdx.y;
    int i0 = iq * 4;
    uint32_t sb = smem_u32(ps);

    // A frags (16 KB @ 65536): hi then lo (in commit group 0)
    cp16(sb + 65536 + tid * 16,        &g_Abh[jt * 512 + tid]);
    cp16(sb + 65536 + (tid+256) * 16,  &g_Abh[jt * 512 + tid + 256]);
    cp16(sb + 73728 + tid * 16,        &g_Abl[jt * 512 + tid]);
    cp16(sb + 73728 + (tid+256) * 16,  &g_Abl[jt * 512 + tid + 256]);
    // B frags for 4 i's (16 KB each), one commit-group per i
    #pragma unroll
    for (int it = 0; it < 4; it++) {
        uint32_t base = sb + it * 16384;
        const uint4* src = g_Tb + (size_t)(i0 + it) * 1024;
        cp16(base + tid * 16,             src + tid);
        cp16(base + (tid + 256) * 16,     src + tid + 256);
        cp16(base + (tid + 512) * 16,     src + tid + 512);
        cp16(base + (tid + 768) * 16,     src + tid + 768);
        CP_COMMIT();
    }

    // bias, permuted layout: col = wn*32 + blk*16 + q*4 + {0..3}
    float4 bvf[2];
    bvf[0] = __ldg((const float4*)(b3 + wn * 32 + q * 4));
    bvf[1] = __ldg((const float4*)(b3 + wn * 32 + 16 + q * 4));

    const uint4* sAH = (const uint4*)(ps + 65536);
    const uint4* sAL = (const uint4*)(ps + 73728);

    #pragma unroll
    for (int it = 0; it < 4; it++) {
        if      (it == 0) asm volatile("cp.async.wait_group 3;" ::: "memory");
        else if (it == 1) asm volatile("cp.async.wait_group 2;" ::: "memory");
        else if (it == 2) asm volatile("cp.async.wait_group 1;" ::: "memory");
        else              asm volatile("cp.async.wait_group 0;" ::: "memory");
        __syncthreads();

        float acc[4][4][4];
        #pragma unroll
        for (int blk = 0; blk < 2; blk++)
            #pragma unroll
            for (int mt = 0; mt < 4; mt++) {
                acc[mt][blk*2][0]   = bvf[blk].x; acc[mt][blk*2][1]   = bvf[blk].y;
                acc[mt][blk*2+1][0] = bvf[blk].z; acc[mt][blk*2+1][1] = bvf[blk].w;
                acc[mt][blk*2][2]   = bvf[blk].x; acc[mt][blk*2][3]   = bvf[blk].y;
                acc[mt][blk*2+1][2] = bvf[blk].z; acc[mt][blk*2+1][3] = bvf[blk].w;
            }

        const uint4* sB = (const uint4*)(ps + it * 16384);
        gemm_compute<4>(sAH, sAL, sB, wm, wn, lane, acc);

        // stores: per (mt, blk, half): float4 at col wn*32+blk*16+q*4
        #pragma unroll
        for (int mt = 0; mt < 4; mt++) {
            int row = jt * 128 + wm * 64 + mt * 16 + (lane >> 2);
            float* o0 = out + ((size_t)(i0 + it) * LSEQ + row) * P + wn * 32 + q * 4;
            #pragma unroll
            for (int blk = 0; blk < 2; blk++) {
                *(float4*)(o0 + blk * 16) =
                    make_float4(acc[mt][blk*2][0], acc[mt][blk*2][1],
                                acc[mt][blk*2+1][0], acc[mt][blk*2+1][1]);
                *(float4*)(o0 + 8 * P + blk * 16) =
                    make_float4(acc[mt][blk*2][2], acc[mt][blk*2][3],
                                acc[mt][blk*2+1][2], acc[mt][blk*2+1][3]);
            }
        }
    }
}

extern "C" void kernel_launch(void* const* d_in, const int* in_sizes, int n_in,
                              void* d_out, int out_size)
{
    const float* seq   = (const float*)d_in[0];
    const float* gamma = (const float*)d_in[1];
    const float* beta  = (const float*)d_in[2];
    const float* w1    = (const float*)d_in[3];
    const float* b1    = (const float*)d_in[4];
    const float* w2    = (const float*)d_in[5];
    const float* b2    = (const float*)d_in[6];
    const float* w3    = (const float*)d_in[7];
    const float* b3    = (const float*)d_in[8];

    cudaFuncSetAttribute(pair_kernel,
                         cudaFuncAttributeMaxDynamicSharedMemorySize, PAIR_SMEM);

    ln_proj_kernel<<<LSEQ, 256>>>(seq, gamma, beta, w1, b1, w2, b2);
    asplit_kernel<<<12, 256>>>();
    tgemm_kernel<<<dim3(3, 64), 256>>>(w3);
    pair_kernel<<<dim3(96, 3), 256, PAIR_SMEM>>>(b3, (float*)d_out);
}